// round 8
// baseline (speedup 1.0000x reference)
#include <cuda_runtime.h>

#define CELL_N 76
#define DRUG_N 764
#define TOT_N  840
#define BATCH  4096
#define NPROT  15970
#define KSPLIT 8
#define KCHUNK 1024  // 8192 / KSPLIT
#define TSQ_N  ((NPROT + 7) / 8)   // 1997 tablesq blocks

typedef unsigned long long ull;

#define PACK2(p, x, y) do { unsigned _ux = __float_as_uint(x), _uy = __float_as_uint(y); \
    asm("mov.b64 %0, {%1, %2};" : "=l"(p) : "r"(_ux), "r"(_uy)); } while (0)
#define FMA2(d, a, b) asm("fma.rn.f32x2 %0, %1, %2, %0;" : "+l"(d) : "l"(a), "l"(b))
#define UNPK(lo, hi, p) do { unsigned _ul, _uh; \
    asm("mov.b64 {%0, %1}, %2;" : "=r"(_ul), "=r"(_uh) : "l"(p)); \
    lo = __uint_as_float(_ul); hi = __uint_as_float(_uh); } while (0)
// d = (hi-of-a, lo-of-b)
#define HILO(d, a, b) asm("{ .reg .b32 al, ah, bl, bh; mov.b64 {al, ah}, %1; " \
    "mov.b64 {bl, bh}, %2; mov.b64 %0, {ah, bl}; }" : "=l"(d) : "l"(a), "l"(b))

// ---------------- scratch (device globals; no allocs allowed) ----------------
__device__ float g_pool1[TOT_N * 4 * 64 * 64];
__device__ float g_pool2[TOT_N * 8 * 32 * 32];
__device__ float g_fcp  [KSPLIT * TOT_N * 64];
__device__ float g_item [TOT_N * 64];
__device__ float g_inter[TOT_N * 128];
__device__ float g_emb  [TOT_N * 64];
__device__ float g_normsq[TOT_N];
__device__ float g_U    [CELL_N * 128];
__device__ float g_tablesq[NPROT];

// ---------------- tablesq (blocks first) + conv1 (merged cell+drug) ----------------
__global__ void __launch_bounds__(256) k_conv1(
        const float* __restrict__ cell_pre, const float* __restrict__ drug_pre,
        const float* __restrict__ w, const float* __restrict__ b,
        const float* __restrict__ table) {
    int blk = blockIdx.x;
    int tid = threadIdx.x;
    if (blk < TSQ_N) {
        int warp = blk * 8 + (tid >> 5);
        int lane = tid & 31;
        if (warp >= NPROT) return;
        const float* r = table + warp * 64;
        float a = r[lane], bb = r[lane + 32];
        float s = a * a + bb * bb;
        #pragma unroll
        for (int o = 16; o; o >>= 1) s += __shfl_down_sync(0xffffffffu, s, o);
        if (lane == 0) g_tablesq[warp] = s;
        return;
    }
    int cblk = blk - TSQ_N;
    int half = cblk & 1;
    int gn;
    const float* x;
    if (cblk < 2 * CELL_N) { gn = cblk >> 1; x = cell_pre + gn * 16384; }
    else { int n = (cblk - 2 * CELL_N) >> 1; gn = CELL_N + n; x = drug_pre + n * 16384; }
    __shared__ float tile[66 * 130];
    float wr[36];
    #pragma unroll
    for (int i = 0; i < 36; i++) wr[i] = w[i];
    float bb[4] = { b[0], b[1], b[2], b[3] };
    int row0 = half * 64 - 1;
    for (int idx = tid; idx < 66 * 130; idx += 256) {
        int r = idx / 130, c = idx - r * 130;
        int y = row0 + r, xx = c - 1;
        tile[idx] = (y >= 0 && y < 128 && (unsigned)xx < 128u) ? x[y * 128 + xx] : 0.f;
    }
    __syncthreads();
    #pragma unroll
    for (int i = 0; i < 8; i++) {
        int pos = tid + i * 256;
        int oy = pos >> 6, ox = pos & 63;
        float p[4][4];
        #pragma unroll
        for (int r = 0; r < 4; r++) {
            const float2* s = (const float2*)&tile[(2 * oy + r) * 130 + 2 * ox];
            float2 a = s[0], d = s[1];
            p[r][0] = a.x; p[r][1] = a.y; p[r][2] = d.x; p[r][3] = d.y;
        }
        #pragma unroll
        for (int oc = 0; oc < 4; oc++) {
            float q00 = bb[oc], q01 = bb[oc], q10 = bb[oc], q11 = bb[oc];
            #pragma unroll
            for (int dy = 0; dy < 3; dy++)
            #pragma unroll
            for (int dx = 0; dx < 3; dx++) {
                float wv = wr[oc * 9 + dy * 3 + dx];
                q00 += p[dy    ][dx    ] * wv;
                q01 += p[dy    ][dx + 1] * wv;
                q10 += p[dy + 1][dx    ] * wv;
                q11 += p[dy + 1][dx + 1] * wv;
            }
            float m = fmaxf(fmaxf(q00, q01), fmaxf(q10, q11));
            g_pool1[((gn * 4 + oc) * 64 + half * 32 + oy) * 64 + ox] = fmaxf(m, 0.f);
        }
    }
}

// ---------------- conv2 (4->8) + relu + pool, f32x2 horizontal-pair packing ----------------
// Accumulators are pairs over adjacent pre-pool columns (the pool pair), so
// operand pairs are contiguous tile columns: direct aligned LDS.64, no dup.
#define C2_STR 68
#define C2_CH  (34 * C2_STR)
__global__ void __launch_bounds__(256, 3) k_conv2(
        const float* __restrict__ w, const float* __restrict__ b) {
    int n = blockIdx.x >> 1, half = blockIdx.x & 1;
    __shared__ float tile[4 * C2_CH];
    __shared__ ull wdup[8 * 36];          // (w,w) duplicated pairs
    int tid = threadIdx.x;
    int row0 = half * 32 - 1;
    for (int idx = tid; idx < 4 * 34 * 66; idx += 256) {
        int c = idx / (34 * 66), rem = idx - c * (34 * 66);
        int r = rem / 66, cc = rem - r * 66;
        int y = row0 + r, xx = cc - 1;
        tile[c * C2_CH + r * C2_STR + cc] =
            ((unsigned)y < 64u && (unsigned)xx < 64u)
          ? g_pool1[((n * 4 + c) * 64 + y) * 64 + xx] : 0.f;
    }
    for (int i = tid; i < 288; i += 256) {
        float v = w[i];
        ull p; PACK2(p, v, v);
        wdup[i] = p;
    }
    __syncthreads();
    int oc = tid >> 5, lane = tid & 31;
    const ull* wp = &wdup[oc * 36];
    float bs = b[oc];
    ull binit; PACK2(binit, bs, bs);
    #pragma unroll
    for (int i = 0; i < 8; i++) {
        int pos = lane + i * 32;
        int oy = pos >> 4, oxp = pos & 15;
        // q0,q1: pooled out 0 (pre cols 4oxp+0..1) rows 0,1
        // q2,q3: pooled out 1 (pre cols 4oxp+2..3) rows 0,1
        ull q0 = binit, q1 = binit, q2 = binit, q3 = binit;
        #pragma unroll
        for (int c = 0; c < 4; c++) {
            ull r[4][3], m0[4], m1[4];
            #pragma unroll
            for (int rr = 0; rr < 4; rr++) {
                const ull* base = (const ull*)&tile[c * C2_CH + (2 * oy + rr) * C2_STR + 4 * oxp];
                r[rr][0] = base[0];          // cols (0,1)
                r[rr][1] = base[1];          // cols (2,3)
                r[rr][2] = base[2];          // cols (4,5)
                HILO(m0[rr], r[rr][0], r[rr][1]);   // cols (1,2)
                HILO(m1[rr], r[rr][1], r[rr][2]);   // cols (3,4)
            }
            #pragma unroll
            for (int dy = 0; dy < 3; dy++) {
                ull w0 = wp[c * 9 + dy * 3 + 0];
                FMA2(q0, r[dy    ][0], w0);
                FMA2(q1, r[dy + 1][0], w0);
                FMA2(q2, r[dy    ][1], w0);
                FMA2(q3, r[dy + 1][1], w0);
                ull w1 = wp[c * 9 + dy * 3 + 1];
                FMA2(q0, m0[dy    ], w1);
                FMA2(q1, m0[dy + 1], w1);
                FMA2(q2, m1[dy    ], w1);
                FMA2(q3, m1[dy + 1], w1);
                ull w2 = wp[c * 9 + dy * 3 + 2];
                FMA2(q0, r[dy    ][1], w2);
                FMA2(q1, r[dy + 1][1], w2);
                FMA2(q2, r[dy    ][2], w2);
                FMA2(q3, r[dy + 1][2], w2);
            }
        }
        float a0, a1, a2, a3, b0, b1, b2, b3;
        UNPK(a0, a1, q0); UNPK(a2, a3, q1);
        UNPK(b0, b1, q2); UNPK(b2, b3, q3);
        float mA = fmaxf(fmaxf(a0, a1), fmaxf(a2, a3));
        float mB = fmaxf(fmaxf(b0, b1), fmaxf(b2, b3));
        float2 v = make_float2(fmaxf(mA, 0.f), fmaxf(mB, 0.f));
        *(float2*)&g_pool2[((n * 8 + oc) * 32 + half * 16 + oy) * 32 + 2 * oxp] = v;
    }
}

// ---------------- FC as tiled GEMM with K-split ----------------
__global__ void __launch_bounds__(256) k_fc(const float* __restrict__ W) {
    int m0 = blockIdx.x * 32;
    int kb = blockIdx.y;
    int k0 = kb * KCHUNK;
    __shared__ float Xs[32][64];
    __shared__ float Ws[64][68];
    int tid = threadIdx.x;
    int tm = tid >> 5, tn = tid & 31;
    float acc[4][2] = {};
    for (int kt = 0; kt < KCHUNK; kt += 64) {
        #pragma unroll
        for (int i = 0; i < 8; i++) {
            int idx = tid + i * 256;
            int r = idx >> 6, c = idx & 63;
            int m = m0 + r;
            Xs[r][c] = (m < TOT_N) ? g_pool2[m * 8192 + k0 + kt + c] : 0.f;
        }
        #pragma unroll
        for (int i = 0; i < 16; i++) {
            int idx = tid + i * 256;
            int j = idx >> 6, c = idx & 63;
            Ws[j][c] = W[j * 8192 + k0 + kt + c];
        }
        __syncthreads();
        #pragma unroll
        for (int kk = 0; kk < 64; kk += 4) {
            float4 w0 = *(const float4*)&Ws[tn     ][kk];
            float4 w1 = *(const float4*)&Ws[tn + 32][kk];
            #pragma unroll
            for (int r = 0; r < 4; r++) {
                float4 xv = *(const float4*)&Xs[tm * 4 + r][kk];
                acc[r][0] += xv.x * w0.x + xv.y * w0.y + xv.z * w0.z + xv.w * w0.w;
                acc[r][1] += xv.x * w1.x + xv.y * w1.y + xv.z * w1.z + xv.w * w1.w;
            }
        }
        __syncthreads();
    }
    #pragma unroll
    for (int r = 0; r < 4; r++) {
        int m = m0 + tm * 4 + r;
        if (m < TOT_N) {
            g_fcp[(kb * TOT_N + m) * 64 + tn     ] = acc[r][0];
            g_fcp[(kb * TOT_N + m) * 64 + tn + 32] = acc[r][1];
        }
    }
}

// ---------------- reduce K-split partials + bias -> g_item (wide grid) ----------------
__global__ void k_fcred(const float* __restrict__ b) {
    int idx = blockIdx.x * blockDim.x + threadIdx.x;
    if (idx >= TOT_N * 64) return;
    float s = b[idx & 63];
    #pragma unroll
    for (int kb = 0; kb < KSPLIT; kb++) s += g_fcp[kb * TOT_N * 64 + idx];
    g_item[idx] = s;
}

// ---------------- standardize: compile-time N, 2 passes ----------------
template<int ROW0, int N>
__device__ __forceinline__ void std_body(float2* red, float* mv, float* sv) {
    int tid = threadIdx.x;
    int j = tid & 63, q = tid >> 6;
    constexpr int R = (N + 15) / 16;
    float s = 0.f, ss = 0.f;
    #pragma unroll
    for (int i = 0; i < R; i++) {
        int n = q + i * 16;
        if (n < N) {
            float v = g_item[(ROW0 + n) * 64 + j];
            s += v;
            ss += v * v;
        }
    }
    red[tid] = make_float2(s, ss);
    __syncthreads();
    if (tid < 64) {
        float S = 0.f, SS = 0.f;
        #pragma unroll
        for (int k = 0; k < 16; k++) {
            float2 r = red[tid + 64 * k];
            S += r.x; SS += r.y;
        }
        float m = S / (float)N;
        float var = (SS - (float)N * m * m) / (float)(N - 1);
        mv[tid] = m;
        sv[tid] = rsqrtf(var);
    }
    __syncthreads();
    float mean = mv[j], inv = sv[j];
    #pragma unroll
    for (int i = 0; i < R; i++) {
        int n = q + i * 16;
        if (n < N) {
            int row = ROW0 + n;
            g_item[row * 64 + j] = (g_item[row * 64 + j] - mean) * inv;
        }
    }
}

__global__ void __launch_bounds__(1024) k_std() {
    __shared__ float2 red[1024];
    __shared__ float mv[64];
    __shared__ float sv[64];
    if (blockIdx.x == 0) std_body<0, CELL_N>(red, mv, sv);
    else                 std_body<CELL_N, DRUG_N>(red, mv, sv);
}

// ---------------- interact: shfl reductions + k-split phase B ----------------
__global__ void k_interact(const int* __restrict__ cell_nbr, const int* __restrict__ drug_nbr,
                           const float* __restrict__ table) {
    int blk = blockIdx.x;
    const int* nbr;
    int nh, item_base, inter_base;
    if (blk < 2 * CELL_N) { nbr = cell_nbr; nh = blk; item_base = 0; inter_base = 0; }
    else { nbr = drug_nbr; nh = blk - 2 * CELL_N; item_base = CELL_N * 64; inter_base = CELL_N * 128; }
    int n = nh >> 1, h = nh & 1;
    __shared__ float rows[128 * 65];
    __shared__ float it[64];
    __shared__ int   idxs[128];
    __shared__ float sc[128];
    __shared__ float wred[8];
    __shared__ float part[128];
    int tid = threadIdx.x;
    int warp = tid >> 5, lane = tid & 31;
    idxs[tid] = nbr[nh * 128 + tid];
    if (tid < 64) it[tid] = g_item[item_base + n * 64 + tid];
    __syncthreads();
    for (int e = tid; e < 128 * 64; e += 128) {
        int k = e >> 6, d = e & 63;
        rows[k * 65 + d] = table[idxs[k] * 64 + d];
    }
    __syncthreads();
    float s = 0.f;
    #pragma unroll 8
    for (int d = 0; d < 64; d++) s += rows[tid * 65 + d] * it[d];
    float m = s;
    #pragma unroll
    for (int o = 16; o; o >>= 1) m = fmaxf(m, __shfl_xor_sync(0xffffffffu, m, o));
    if (lane == 0) wred[warp] = m;
    __syncthreads();
    float mx = fmaxf(fmaxf(wred[0], wred[1]), fmaxf(wred[2], wred[3]));
    float e = expf(s - mx);
    sc[tid] = e;
    float t = e;
    #pragma unroll
    for (int o = 16; o; o >>= 1) t += __shfl_xor_sync(0xffffffffu, t, o);
    if (lane == 0) wred[4 + warp] = t;
    __syncthreads();
    float inv = 1.f / (wred[4] + wred[5] + wred[6] + wred[7]);
    int d = tid & 63, kh = tid >> 6;
    float o = 0.f;
    int kb = kh * 64;
    #pragma unroll 8
    for (int k2 = 0; k2 < 64; k2++) {
        int k = kb + k2;
        o += sc[k] * rows[k * 65 + d];
    }
    part[tid] = o;
    __syncthreads();
    if (tid < 64)
        g_inter[inter_base + n * 128 + h * 64 + tid] = (part[tid] + part[tid + 64]) * inv;
}

// ---------------- agg (k-split) + normsq + (cells) U ----------------
__global__ void k_agg(const float* __restrict__ W, const float* __restrict__ b,
                      const float* __restrict__ combw) {
    int n = blockIdx.x;
    __shared__ float xr[128];
    __shared__ float e[64];
    __shared__ float red[64];
    __shared__ float part[128];
    int tid = threadIdx.x;
    xr[tid] = g_inter[n * 128 + tid];
    __syncthreads();
    int j = tid & 63, kh = tid >> 6;
    float s = 0.f;
    int tb = kh * 64;
    #pragma unroll 8
    for (int t2 = 0; t2 < 64; t2++) {
        int t = tb + t2;
        s += W[j * 128 + t] * xr[t];
    }
    part[tid] = s;
    __syncthreads();
    if (tid < 64) {
        float v = part[tid] + part[tid + 64] + b[tid];
        g_emb[n * 64 + tid] = v;
        e[tid] = v;
        red[tid] = v * v;
    }
    __syncthreads();
    if (tid < 32) {
        float v = red[tid] + red[tid + 32];
        #pragma unroll
        for (int o = 16; o; o >>= 1) v += __shfl_down_sync(0xffffffffu, v, o);
        if (tid == 0) g_normsq[n] = v;
    }
    if (n < CELL_N) {
        float s2 = 0.f;
        #pragma unroll 8
        for (int j2 = 0; j2 < 64; j2++) s2 += combw[j2 * 128 + tid] * e[j2];
        g_U[n * 128 + tid] = s2;
    }
}

// ---------------- score (blocks 0..15) + loss (block 16), one launch ----------------
__global__ void __launch_bounds__(256) k_scoreloss(
        const int* __restrict__ data, const int* __restrict__ cell_nbr,
        const int* __restrict__ drug_nbr, float* __restrict__ out, int loss_idx) {
    int blk = blockIdx.x;
    int tid = threadIdx.x;
    if (blk < 16) {
        int bidx = blk * 256 + tid;
        int c  = data[3 * bidx];
        int d1 = data[3 * bidx + 1];
        int d2 = data[3 * bidx + 2];
        const float* e1 = g_emb + (CELL_N + d1) * 64;
        const float* e2 = g_emb + (CELL_N + d2) * 64;
        const float* u  = g_U + c * 128;
        float s = 0.f;
        #pragma unroll 8
        for (int t = 0; t < 64; t++) {
            float a = e1[t], bb = e2[t];
            s += a * u[t] + bb * u[64 + t] - a * bb;
        }
        out[bidx] = s;
        return;
    }
    __shared__ float nsq[TOT_N];
    __shared__ float red[256];
    for (int i = tid; i < TOT_N; i += 256) nsq[i] = g_normsq[i];
    __syncthreads();
    float ir = 0.f;
    for (int bidx = tid; bidx < BATCH; bidx += 256) {
        int c  = data[3 * bidx];
        int d1 = data[3 * bidx + 1];
        int d2 = data[3 * bidx + 2];
        ir += nsq[c] + nsq[CELL_N + d1] + nsq[CELL_N + d2];
    }
    float nr = 0.f;
    for (int e = tid; e < 1536; e += 256) {
        int set = e >> 8, off = e & 255;
        int hop = set / 3, which = set - hop * 3;
        int nodeidx = data[hop * 3 + which];
        int p = (which == 0) ? cell_nbr[nodeidx * 256 + off] : drug_nbr[nodeidx * 256 + off];
        nr += g_tablesq[p];
    }
    red[tid] = 0.5f * ir + 0.5f * nr;
    __syncthreads();
    #pragma unroll
    for (int off = 128; off; off >>= 1) {
        if (tid < off) red[tid] += red[tid + off];
        __syncthreads();
    }
    if (tid == 0) out[loss_idx] = 1e-6f * red[0] / (float)BATCH;
}

// ---------------- launch ----------------
extern "C" void kernel_launch(void* const* d_in, const int* in_sizes, int n_in,
                              void* d_out, int out_size) {
    const int*   data     = (const int*)  d_in[0];
    const int*   cell_nbr = (const int*)  d_in[1];
    const int*   drug_nbr = (const int*)  d_in[2];
    const float* table    = (const float*)d_in[3];
    const float* cell_pre = (const float*)d_in[4];
    const float* drug_pre = (const float*)d_in[5];
    const float* c1w      = (const float*)d_in[6];
    const float* c1b      = (const float*)d_in[7];
    const float* c2w      = (const float*)d_in[8];
    const float* c2b      = (const float*)d_in[9];
    const float* ow       = (const float*)d_in[10];
    const float* ob       = (const float*)d_in[11];
    const float* aw       = (const float*)d_in[12];
    const float* ab       = (const float*)d_in[13];
    const float* cw       = (const float*)d_in[14];
    float* out = (float*)d_out;

    k_conv1<<<TSQ_N + TOT_N * 2, 256>>>(cell_pre, drug_pre, c1w, c1b, table);
    k_conv2<<<TOT_N * 2, 256>>>(c2w, c2b);

    dim3 fcg(27, KSPLIT);
    k_fc<<<fcg, 256>>>(ow);
    k_fcred<<<(TOT_N * 64 + 255) / 256, 256>>>(ob);
    k_std<<<2, 1024>>>();

    k_interact<<<TOT_N * 2, 128>>>(cell_nbr, drug_nbr, table);
    k_agg<<<TOT_N, 128>>>(aw, ab, cw);
    k_scoreloss<<<17, 256>>>(data, cell_nbr, drug_nbr, out, out_size - 1);
}

// round 9
// speedup vs baseline: 1.0916x; 1.0916x over previous
#include <cuda_runtime.h>

#define CELL_N 76
#define DRUG_N 764
#define TOT_N  840
#define BATCH  4096
#define NPROT  15970
#define KSPLIT 8
#define KCHUNK 1024  // 8192 / KSPLIT
#define TSQ_N  ((NPROT + 7) / 8)   // 1997 tablesq blocks

// ---------------- scratch (device globals; no allocs allowed) ----------------
__device__ float g_pool1[TOT_N * 4 * 64 * 64];
__device__ float g_pool2[TOT_N * 8 * 32 * 32];
__device__ float g_fcp  [KSPLIT * TOT_N * 64];
__device__ float g_item [TOT_N * 64];
__device__ float g_emb  [TOT_N * 64];
__device__ float g_normsq[TOT_N];
__device__ float g_U    [CELL_N * 128];
__device__ float g_tablesq[NPROT];

// ---------------- tablesq (blocks first) + conv1 (merged cell+drug) ----------------
__global__ void __launch_bounds__(256) k_conv1(
        const float* __restrict__ cell_pre, const float* __restrict__ drug_pre,
        const float* __restrict__ w, const float* __restrict__ b,
        const float* __restrict__ table) {
    int blk = blockIdx.x;
    int tid = threadIdx.x;
    if (blk < TSQ_N) {
        int warp = blk * 8 + (tid >> 5);
        int lane = tid & 31;
        if (warp >= NPROT) return;
        const float* r = table + warp * 64;
        float a = r[lane], bb = r[lane + 32];
        float s = a * a + bb * bb;
        #pragma unroll
        for (int o = 16; o; o >>= 1) s += __shfl_down_sync(0xffffffffu, s, o);
        if (lane == 0) g_tablesq[warp] = s;
        return;
    }
    int cblk = blk - TSQ_N;
    int half = cblk & 1;
    int gn;
    const float* x;
    if (cblk < 2 * CELL_N) { gn = cblk >> 1; x = cell_pre + gn * 16384; }
    else { int n = (cblk - 2 * CELL_N) >> 1; gn = CELL_N + n; x = drug_pre + n * 16384; }
    __shared__ float tile[66 * 130];
    float wr[36];
    #pragma unroll
    for (int i = 0; i < 36; i++) wr[i] = w[i];
    float bb[4] = { b[0], b[1], b[2], b[3] };
    int row0 = half * 64 - 1;
    for (int idx = tid; idx < 66 * 130; idx += 256) {
        int r = idx / 130, c = idx - r * 130;
        int y = row0 + r, xx = c - 1;
        tile[idx] = (y >= 0 && y < 128 && (unsigned)xx < 128u) ? x[y * 128 + xx] : 0.f;
    }
    __syncthreads();
    #pragma unroll
    for (int i = 0; i < 8; i++) {
        int pos = tid + i * 256;
        int oy = pos >> 6, ox = pos & 63;
        float p[4][4];
        #pragma unroll
        for (int r = 0; r < 4; r++) {
            const float2* s = (const float2*)&tile[(2 * oy + r) * 130 + 2 * ox];
            float2 a = s[0], d = s[1];
            p[r][0] = a.x; p[r][1] = a.y; p[r][2] = d.x; p[r][3] = d.y;
        }
        #pragma unroll
        for (int oc = 0; oc < 4; oc++) {
            float q00 = bb[oc], q01 = bb[oc], q10 = bb[oc], q11 = bb[oc];
            #pragma unroll
            for (int dy = 0; dy < 3; dy++)
            #pragma unroll
            for (int dx = 0; dx < 3; dx++) {
                float wv = wr[oc * 9 + dy * 3 + dx];
                q00 += p[dy    ][dx    ] * wv;
                q01 += p[dy    ][dx + 1] * wv;
                q10 += p[dy + 1][dx    ] * wv;
                q11 += p[dy + 1][dx + 1] * wv;
            }
            float m = fmaxf(fmaxf(q00, q01), fmaxf(q10, q11));
            g_pool1[((gn * 4 + oc) * 64 + half * 32 + oy) * 64 + ox] = fmaxf(m, 0.f);
        }
    }
}

// ---------------- conv2 (4->8) + relu + pool, scalar pair-output blocking (R7) ----------------
#define C2_STR 68
#define C2_CH  (34 * C2_STR)
__global__ void __launch_bounds__(256, 3) k_conv2(
        const float* __restrict__ w, const float* __restrict__ b) {
    int n = blockIdx.x >> 1, half = blockIdx.x & 1;
    __shared__ float tile[4 * C2_CH];
    int tid = threadIdx.x;
    int row0 = half * 32 - 1;
    for (int idx = tid; idx < 4 * 34 * 66; idx += 256) {
        int c = idx / (34 * 66), rem = idx - c * (34 * 66);
        int r = rem / 66, cc = rem - r * 66;
        int y = row0 + r, xx = cc - 1;
        tile[c * C2_CH + r * C2_STR + cc] =
            ((unsigned)y < 64u && (unsigned)xx < 64u)
          ? g_pool1[((n * 4 + c) * 64 + y) * 64 + xx] : 0.f;
    }
    __syncthreads();
    int oc = tid >> 5, lane = tid & 31;
    float wr[36];
    #pragma unroll
    for (int i = 0; i < 36; i++) wr[i] = w[oc * 36 + i];
    float bs = b[oc];
    #pragma unroll
    for (int i = 0; i < 8; i++) {
        int pos = lane + i * 32;
        int oy = pos >> 4, oxp = pos & 15;
        float q[8];
        #pragma unroll
        for (int k = 0; k < 8; k++) q[k] = bs;
        #pragma unroll
        for (int c = 0; c < 4; c++) {
            float pt[4][6];
            #pragma unroll
            for (int rr = 0; rr < 4; rr++) {
                const float* base = &tile[c * C2_CH + (2 * oy + rr) * C2_STR + 4 * oxp];
                float4 a = *(const float4*)base;
                float2 b2 = *(const float2*)(base + 4);
                pt[rr][0] = a.x; pt[rr][1] = a.y; pt[rr][2] = a.z;
                pt[rr][3] = a.w; pt[rr][4] = b2.x; pt[rr][5] = b2.y;
            }
            #pragma unroll
            for (int dy = 0; dy < 3; dy++)
            #pragma unroll
            for (int dx = 0; dx < 3; dx++) {
                float wv = wr[c * 9 + dy * 3 + dx];
                q[0] += pt[dy    ][dx    ] * wv;
                q[1] += pt[dy    ][dx + 1] * wv;
                q[2] += pt[dy + 1][dx    ] * wv;
                q[3] += pt[dy + 1][dx + 1] * wv;
                q[4] += pt[dy    ][dx + 2] * wv;
                q[5] += pt[dy    ][dx + 3] * wv;
                q[6] += pt[dy + 1][dx + 2] * wv;
                q[7] += pt[dy + 1][dx + 3] * wv;
            }
        }
        float m0 = fmaxf(fmaxf(q[0], q[1]), fmaxf(q[2], q[3]));
        float m1 = fmaxf(fmaxf(q[4], q[5]), fmaxf(q[6], q[7]));
        float2 v = make_float2(fmaxf(m0, 0.f), fmaxf(m1, 0.f));
        *(float2*)&g_pool2[((n * 8 + oc) * 32 + half * 16 + oy) * 32 + 2 * oxp] = v;
    }
}

// ---------------- FC as tiled GEMM with K-split ----------------
__global__ void __launch_bounds__(256) k_fc(const float* __restrict__ W) {
    int m0 = blockIdx.x * 32;
    int kb = blockIdx.y;
    int k0 = kb * KCHUNK;
    __shared__ float Xs[32][64];
    __shared__ float Ws[64][68];
    int tid = threadIdx.x;
    int tm = tid >> 5, tn = tid & 31;
    float acc[4][2] = {};
    for (int kt = 0; kt < KCHUNK; kt += 64) {
        #pragma unroll
        for (int i = 0; i < 8; i++) {
            int idx = tid + i * 256;
            int r = idx >> 6, c = idx & 63;
            int m = m0 + r;
            Xs[r][c] = (m < TOT_N) ? g_pool2[m * 8192 + k0 + kt + c] : 0.f;
        }
        #pragma unroll
        for (int i = 0; i < 16; i++) {
            int idx = tid + i * 256;
            int j = idx >> 6, c = idx & 63;
            Ws[j][c] = W[j * 8192 + k0 + kt + c];
        }
        __syncthreads();
        #pragma unroll
        for (int kk = 0; kk < 64; kk += 4) {
            float4 w0 = *(const float4*)&Ws[tn     ][kk];
            float4 w1 = *(const float4*)&Ws[tn + 32][kk];
            #pragma unroll
            for (int r = 0; r < 4; r++) {
                float4 xv = *(const float4*)&Xs[tm * 4 + r][kk];
                acc[r][0] += xv.x * w0.x + xv.y * w0.y + xv.z * w0.z + xv.w * w0.w;
                acc[r][1] += xv.x * w1.x + xv.y * w1.y + xv.z * w1.z + xv.w * w1.w;
            }
        }
        __syncthreads();
    }
    #pragma unroll
    for (int r = 0; r < 4; r++) {
        int m = m0 + tm * 4 + r;
        if (m < TOT_N) {
            g_fcp[(kb * TOT_N + m) * 64 + tn     ] = acc[r][0];
            g_fcp[(kb * TOT_N + m) * 64 + tn + 32] = acc[r][1];
        }
    }
}

// ---------------- reduce K-split partials + bias -> g_item (float4) ----------------
__global__ void k_fcred(const float* __restrict__ b) {
    int v = blockIdx.x * blockDim.x + threadIdx.x;     // float4 index
    if (v >= TOT_N * 16) return;
    int j4 = (v & 15) * 4;
    float4 s = *(const float4*)&b[j4];
    #pragma unroll
    for (int kb = 0; kb < KSPLIT; kb++) {
        float4 p = *(const float4*)&g_fcp[kb * TOT_N * 64 + v * 4];
        s.x += p.x; s.y += p.y; s.z += p.z; s.w += p.w;
    }
    *(float4*)&g_item[v * 4] = s;
}

// ---------------- standardize: compile-time N, 2 passes ----------------
template<int ROW0, int N>
__device__ __forceinline__ void std_body(float2* red, float* mv, float* sv) {
    int tid = threadIdx.x;
    int j = tid & 63, q = tid >> 6;
    constexpr int R = (N + 15) / 16;
    float s = 0.f, ss = 0.f;
    #pragma unroll
    for (int i = 0; i < R; i++) {
        int n = q + i * 16;
        if (n < N) {
            float v = g_item[(ROW0 + n) * 64 + j];
            s += v;
            ss += v * v;
        }
    }
    red[tid] = make_float2(s, ss);
    __syncthreads();
    if (tid < 64) {
        float S = 0.f, SS = 0.f;
        #pragma unroll
        for (int k = 0; k < 16; k++) {
            float2 r = red[tid + 64 * k];
            S += r.x; SS += r.y;
        }
        float m = S / (float)N;
        float var = (SS - (float)N * m * m) / (float)(N - 1);
        mv[tid] = m;
        sv[tid] = rsqrtf(var);
    }
    __syncthreads();
    float mean = mv[j], inv = sv[j];
    #pragma unroll
    for (int i = 0; i < R; i++) {
        int n = q + i * 16;
        if (n < N) {
            int row = ROW0 + n;
            g_item[row * 64 + j] = (g_item[row * 64 + j] - mean) * inv;
        }
    }
}

__global__ void __launch_bounds__(1024) k_std() {
    __shared__ float2 red[1024];
    __shared__ float mv[64];
    __shared__ float sv[64];
    if (blockIdx.x == 0) std_body<0, CELL_N>(red, mv, sv);
    else                 std_body<CELL_N, DRUG_N>(red, mv, sv);
}

// ---------------- interact + agg fused: block per item n, 256 threads ----------------
// smem rows: 2 hops x 128 k x 64 d (stride 65). Phase A: 256 threads = one
// (hop,k) dot each. Softmax per 128-thread hop half. Phase B: k-split weighted
// sum -> xr[128] in smem. Then agg GEMV + normsq + (cells) U, no global trip.
#define IA_ROWS (128 * 65)
__global__ void __launch_bounds__(256) k_interagg(
        const int* __restrict__ cell_nbr, const int* __restrict__ drug_nbr,
        const float* __restrict__ table,
        const float* __restrict__ W, const float* __restrict__ b,
        const float* __restrict__ combw) {
    int n = blockIdx.x;
    const int* nbr;
    int item_base;
    if (n < CELL_N) { nbr = cell_nbr + n * 256; item_base = n * 64; }
    else { nbr = drug_nbr + (n - CELL_N) * 256; item_base = n * 64; }

    extern __shared__ float sm[];
    float* rows = sm;                      // 2 * IA_ROWS
    float* it   = sm + 2 * IA_ROWS;        // 64
    float* sc   = it + 64;                 // 256
    float* xr   = sc + 256;                // 128
    float* wred = xr + 128;                // 16
    float* part = wred + 16;               // 256
    __shared__ int idxs[256];

    int tid = threadIdx.x;
    int warp = tid >> 5, lane = tid & 31;
    int hop = tid >> 7, wg = tid & 127;
    idxs[tid] = nbr[tid];
    if (tid < 64) it[tid] = g_item[item_base + tid];
    __syncthreads();
    // gather 2*128 rows of 64
    for (int e = tid; e < 2 * 128 * 64; e += 256) {
        int hk = e >> 6, d = e & 63;           // hk in [0,256)
        int h = hk >> 7, k = hk & 127;
        rows[h * IA_ROWS + k * 65 + d] = table[idxs[h * 128 + k] * 64 + d];
    }
    __syncthreads();
    // phase A: one dot per thread (hop, k=wg)
    const float* myrow = &rows[hop * IA_ROWS + wg * 65];
    float s = 0.f;
    #pragma unroll 8
    for (int d = 0; d < 64; d++) s += myrow[d] * it[d];
    // per-hop max: warps 0-3 hop0, 4-7 hop1
    float m = s;
    #pragma unroll
    for (int o = 16; o; o >>= 1) m = fmaxf(m, __shfl_xor_sync(0xffffffffu, m, o));
    if (lane == 0) wred[warp] = m;
    __syncthreads();
    int wb = (hop << 2);
    float mx = fmaxf(fmaxf(wred[wb], wred[wb + 1]), fmaxf(wred[wb + 2], wred[wb + 3]));
    float e = expf(s - mx);
    sc[tid] = e;
    float t = e;
    #pragma unroll
    for (int o = 16; o; o >>= 1) t += __shfl_xor_sync(0xffffffffu, t, o);
    if (lane == 0) wred[8 + warp] = t;
    __syncthreads();
    float inv = 1.f / (wred[8 + wb] + wred[9 + wb] + wred[10 + wb] + wred[11 + wb]);
    // phase B: within hop half, d = wg&63, kh = wg>>6
    int d = wg & 63, kh = wg >> 6;
    const float* rb = &rows[hop * IA_ROWS + (kh * 64) * 65];
    const float* sb = &sc[hop * 128 + kh * 64];
    float o = 0.f;
    #pragma unroll 8
    for (int k2 = 0; k2 < 64; k2++) o += sb[k2] * rb[k2 * 65 + d];
    part[tid] = o;
    __syncthreads();
    if (wg < 64) {
        int base = hop << 7;
        xr[hop * 64 + wg] = (part[base + wg] + part[base + 64 + wg]) * inv;
    }
    __syncthreads();
    // agg: 4-way t-split, j = tid&63, slice = tid>>6 (32 t each)
    int j = tid & 63, sl = tid >> 6;
    float ag = 0.f;
    const float* wrow = &W[j * 128 + sl * 32];
    const float* xs = &xr[sl * 32];
    #pragma unroll 8
    for (int t2 = 0; t2 < 32; t2++) ag += wrow[t2] * xs[t2];
    part[tid] = ag;
    __syncthreads();
    if (tid < 64) {
        float v = part[tid] + part[tid + 64] + part[tid + 128] + part[tid + 192] + b[tid];
        g_emb[n * 64 + tid] = v;
        it[tid] = v;                       // reuse as emb cache
        sc[tid] = v * v;
    }
    __syncthreads();
    if (tid < 32) {
        float v = sc[tid] + sc[tid + 32];
        #pragma unroll
        for (int o2 = 16; o2; o2 >>= 1) v += __shfl_down_sync(0xffffffffu, v, o2);
        if (tid == 0) g_normsq[n] = v;
    }
    if (n < CELL_N && tid < 128) {
        float s2 = 0.f;
        #pragma unroll 8
        for (int j2 = 0; j2 < 64; j2++) s2 += combw[j2 * 128 + tid] * it[j2];
        g_U[n * 128 + tid] = s2;
    }
}

// ---------------- score (blocks 0..15) + loss (block 16), one launch ----------------
__global__ void __launch_bounds__(256) k_scoreloss(
        const int* __restrict__ data, const int* __restrict__ cell_nbr,
        const int* __restrict__ drug_nbr, float* __restrict__ out, int loss_idx) {
    int blk = blockIdx.x;
    int tid = threadIdx.x;
    if (blk < 16) {
        int bidx = blk * 256 + tid;
        int c  = data[3 * bidx];
        int d1 = data[3 * bidx + 1];
        int d2 = data[3 * bidx + 2];
        const float* e1 = g_emb + (CELL_N + d1) * 64;
        const float* e2 = g_emb + (CELL_N + d2) * 64;
        const float* u  = g_U + c * 128;
        float s = 0.f;
        #pragma unroll 8
        for (int t = 0; t < 64; t++) {
            float a = e1[t], bb = e2[t];
            s += a * u[t] + bb * u[64 + t] - a * bb;
        }
        out[bidx] = s;
        return;
    }
    __shared__ float nsq[TOT_N];
    __shared__ float red[256];
    for (int i = tid; i < TOT_N; i += 256) nsq[i] = g_normsq[i];
    __syncthreads();
    float ir = 0.f;
    for (int bidx = tid; bidx < BATCH; bidx += 256) {
        int c  = data[3 * bidx];
        int d1 = data[3 * bidx + 1];
        int d2 = data[3 * bidx + 2];
        ir += nsq[c] + nsq[CELL_N + d1] + nsq[CELL_N + d2];
    }
    float nr = 0.f;
    for (int e = tid; e < 1536; e += 256) {
        int set = e >> 8, off = e & 255;
        int hop = set / 3, which = set - hop * 3;
        int nodeidx = data[hop * 3 + which];
        int p = (which == 0) ? cell_nbr[nodeidx * 256 + off] : drug_nbr[nodeidx * 256 + off];
        nr += g_tablesq[p];
    }
    red[tid] = 0.5f * ir + 0.5f * nr;
    __syncthreads();
    #pragma unroll
    for (int off = 128; off; off >>= 1) {
        if (tid < off) red[tid] += red[tid + off];
        __syncthreads();
    }
    if (tid == 0) out[loss_idx] = 1e-6f * red[0] / (float)BATCH;
}

// ---------------- launch ----------------
extern "C" void kernel_launch(void* const* d_in, const int* in_sizes, int n_in,
                              void* d_out, int out_size) {
    const int*   data     = (const int*)  d_in[0];
    const int*   cell_nbr = (const int*)  d_in[1];
    const int*   drug_nbr = (const int*)  d_in[2];
    const float* table    = (const float*)d_in[3];
    const float* cell_pre = (const float*)d_in[4];
    const float* drug_pre = (const float*)d_in[5];
    const float* c1w      = (const float*)d_in[6];
    const float* c1b      = (const float*)d_in[7];
    const float* c2w      = (const float*)d_in[8];
    const float* c2b      = (const float*)d_in[9];
    const float* ow       = (const float*)d_in[10];
    const float* ob       = (const float*)d_in[11];
    const float* aw       = (const float*)d_in[12];
    const float* ab       = (const float*)d_in[13];
    const float* cw       = (const float*)d_in[14];
    float* out = (float*)d_out;

    // interagg dynamic smem: rows + it + sc + xr + wred + part
    int ia_smem = (2 * IA_ROWS + 64 + 256 + 128 + 16 + 256) * 4;
    cudaFuncSetAttribute(k_interagg, cudaFuncAttributeMaxDynamicSharedMemorySize, ia_smem);

    k_conv1<<<TSQ_N + TOT_N * 2, 256>>>(cell_pre, drug_pre, c1w, c1b, table);
    k_conv2<<<TOT_N * 2, 256>>>(c2w, c2b);

    dim3 fcg(27, KSPLIT);
    k_fc<<<fcg, 256>>>(ow);
    k_fcred<<<(TOT_N * 16 + 255) / 256, 256>>>(ob);
    k_std<<<2, 1024>>>();

    k_interagg<<<TOT_N, 256, ia_smem>>>(cell_nbr, drug_nbr, table, aw, ab, cw);
    k_scoreloss<<<17, 256>>>(data, cell_nbr, drug_nbr, out, out_size - 1);
}

// round 10
// speedup vs baseline: 1.2260x; 1.1231x over previous
#include <cuda_runtime.h>

#define CELL_N 76
#define DRUG_N 764
#define TOT_N  840
#define BATCH  4096
#define NPROT  15970
#define KSPLIT 8
#define KCHUNK 1024  // 8192 / KSPLIT
#define TSQ_N  ((NPROT + 7) / 8)   // 1997 tablesq blocks

// ---------------- scratch (device globals; no allocs allowed) ----------------
__device__ float g_pool1[TOT_N * 4 * 64 * 64];
__device__ float g_pool2[TOT_N * 8 * 32 * 32];
__device__ float g_fcp  [KSPLIT * TOT_N * 64];
__device__ float g_item [TOT_N * 64];
__device__ float g_emb  [TOT_N * 64];
__device__ float g_normsq[TOT_N];
__device__ float g_U    [CELL_N * 128];
__device__ float g_tablesq[NPROT];

// ---------------- tablesq (blocks first) + conv1 (merged cell+drug) ----------------
// conv1 weights windowed from smem: 9 live weight regs -> 5 CTAs/SM.
__global__ void __launch_bounds__(256, 5) k_conv1(
        const float* __restrict__ cell_pre, const float* __restrict__ drug_pre,
        const float* __restrict__ w, const float* __restrict__ b,
        const float* __restrict__ table) {
    int blk = blockIdx.x;
    int tid = threadIdx.x;
    if (blk < TSQ_N) {
        int warp = blk * 8 + (tid >> 5);
        int lane = tid & 31;
        if (warp >= NPROT) return;
        const float* r = table + warp * 64;
        float a = r[lane], bb = r[lane + 32];
        float s = a * a + bb * bb;
        #pragma unroll
        for (int o = 16; o; o >>= 1) s += __shfl_down_sync(0xffffffffu, s, o);
        if (lane == 0) g_tablesq[warp] = s;
        return;
    }
    int cblk = blk - TSQ_N;
    int half = cblk & 1;
    int gn;
    const float* x;
    if (cblk < 2 * CELL_N) { gn = cblk >> 1; x = cell_pre + gn * 16384; }
    else { int n = (cblk - 2 * CELL_N) >> 1; gn = CELL_N + n; x = drug_pre + n * 16384; }
    __shared__ float tile[66 * 130];
    __shared__ float ws1[36];
    __shared__ float bs1[4];
    if (tid < 36) ws1[tid] = w[tid];
    if (tid < 4)  bs1[tid] = b[tid];
    int row0 = half * 64 - 1;
    for (int idx = tid; idx < 66 * 130; idx += 256) {
        int r = idx / 130, c = idx - r * 130;
        int y = row0 + r, xx = c - 1;
        tile[idx] = (y >= 0 && y < 128 && (unsigned)xx < 128u) ? x[y * 128 + xx] : 0.f;
    }
    __syncthreads();
    #pragma unroll
    for (int i = 0; i < 8; i++) {
        int pos = tid + i * 256;
        int oy = pos >> 6, ox = pos & 63;
        float p[4][4];
        #pragma unroll
        for (int r = 0; r < 4; r++) {
            const float2* s = (const float2*)&tile[(2 * oy + r) * 130 + 2 * ox];
            float2 a = s[0], d = s[1];
            p[r][0] = a.x; p[r][1] = a.y; p[r][2] = d.x; p[r][3] = d.y;
        }
        #pragma unroll
        for (int oc = 0; oc < 4; oc++) {
            float wr[9];
            #pragma unroll
            for (int t = 0; t < 9; t++) wr[t] = ws1[oc * 9 + t];
            float bv = bs1[oc];
            float q00 = bv, q01 = bv, q10 = bv, q11 = bv;
            #pragma unroll
            for (int dy = 0; dy < 3; dy++)
            #pragma unroll
            for (int dx = 0; dx < 3; dx++) {
                float wv = wr[dy * 3 + dx];
                q00 += p[dy    ][dx    ] * wv;
                q01 += p[dy    ][dx + 1] * wv;
                q10 += p[dy + 1][dx    ] * wv;
                q11 += p[dy + 1][dx + 1] * wv;
            }
            float m = fmaxf(fmaxf(q00, q01), fmaxf(q10, q11));
            g_pool1[((gn * 4 + oc) * 64 + half * 32 + oy) * 64 + ox] = fmaxf(m, 0.f);
        }
    }
}

// ---------------- conv2 (4->8) + relu + pool, weight window -> 4 CTAs/SM ----------------
#define C2_STR 68
#define C2_CH  (34 * C2_STR)
__global__ void __launch_bounds__(256, 4) k_conv2(
        const float* __restrict__ w, const float* __restrict__ b) {
    int n = blockIdx.x >> 1, half = blockIdx.x & 1;
    __shared__ float tile[4 * C2_CH];
    __shared__ float ws[288];
    int tid = threadIdx.x;
    int row0 = half * 32 - 1;
    for (int i = tid; i < 288; i += 256) ws[i] = w[i];
    for (int idx = tid; idx < 4 * 34 * 66; idx += 256) {
        int c = idx / (34 * 66), rem = idx - c * (34 * 66);
        int r = rem / 66, cc = rem - r * 66;
        int y = row0 + r, xx = cc - 1;
        tile[c * C2_CH + r * C2_STR + cc] =
            ((unsigned)y < 64u && (unsigned)xx < 64u)
          ? g_pool1[((n * 4 + c) * 64 + y) * 64 + xx] : 0.f;
    }
    __syncthreads();
    int oc = tid >> 5, lane = tid & 31;
    float bs = b[oc];
    #pragma unroll
    for (int i = 0; i < 8; i++) {
        int pos = lane + i * 32;
        int oy = pos >> 4, oxp = pos & 15;
        float q[8];
        #pragma unroll
        for (int k = 0; k < 8; k++) q[k] = bs;
        #pragma unroll
        for (int c = 0; c < 4; c++) {
            float pt[4][6];
            #pragma unroll
            for (int rr = 0; rr < 4; rr++) {
                const float* base = &tile[c * C2_CH + (2 * oy + rr) * C2_STR + 4 * oxp];
                float4 a = *(const float4*)base;
                float2 b2 = *(const float2*)(base + 4);
                pt[rr][0] = a.x; pt[rr][1] = a.y; pt[rr][2] = a.z;
                pt[rr][3] = a.w; pt[rr][4] = b2.x; pt[rr][5] = b2.y;
            }
            float wr[9];
            #pragma unroll
            for (int t = 0; t < 9; t++) wr[t] = ws[oc * 36 + c * 9 + t];
            #pragma unroll
            for (int dy = 0; dy < 3; dy++)
            #pragma unroll
            for (int dx = 0; dx < 3; dx++) {
                float wv = wr[dy * 3 + dx];
                q[0] += pt[dy    ][dx    ] * wv;
                q[1] += pt[dy    ][dx + 1] * wv;
                q[2] += pt[dy + 1][dx    ] * wv;
                q[3] += pt[dy + 1][dx + 1] * wv;
                q[4] += pt[dy    ][dx + 2] * wv;
                q[5] += pt[dy    ][dx + 3] * wv;
                q[6] += pt[dy + 1][dx + 2] * wv;
                q[7] += pt[dy + 1][dx + 3] * wv;
            }
        }
        float m0 = fmaxf(fmaxf(q[0], q[1]), fmaxf(q[2], q[3]));
        float m1 = fmaxf(fmaxf(q[4], q[5]), fmaxf(q[6], q[7]));
        float2 v = make_float2(fmaxf(m0, 0.f), fmaxf(m1, 0.f));
        *(float2*)&g_pool2[((n * 8 + oc) * 32 + half * 16 + oy) * 32 + 2 * oxp] = v;
    }
}

// ---------------- FC as tiled GEMM with K-split ----------------
__global__ void __launch_bounds__(256) k_fc(const float* __restrict__ W) {
    int m0 = blockIdx.x * 32;
    int kb = blockIdx.y;
    int k0 = kb * KCHUNK;
    __shared__ float Xs[32][64];
    __shared__ float Ws[64][68];
    int tid = threadIdx.x;
    int tm = tid >> 5, tn = tid & 31;
    float acc[4][2] = {};
    for (int kt = 0; kt < KCHUNK; kt += 64) {
        #pragma unroll
        for (int i = 0; i < 8; i++) {
            int idx = tid + i * 256;
            int r = idx >> 6, c = idx & 63;
            int m = m0 + r;
            Xs[r][c] = (m < TOT_N) ? g_pool2[m * 8192 + k0 + kt + c] : 0.f;
        }
        #pragma unroll
        for (int i = 0; i < 16; i++) {
            int idx = tid + i * 256;
            int j = idx >> 6, c = idx & 63;
            Ws[j][c] = W[j * 8192 + k0 + kt + c];
        }
        __syncthreads();
        #pragma unroll
        for (int kk = 0; kk < 64; kk += 4) {
            float4 w0 = *(const float4*)&Ws[tn     ][kk];
            float4 w1 = *(const float4*)&Ws[tn + 32][kk];
            #pragma unroll
            for (int r = 0; r < 4; r++) {
                float4 xv = *(const float4*)&Xs[tm * 4 + r][kk];
                acc[r][0] += xv.x * w0.x + xv.y * w0.y + xv.z * w0.z + xv.w * w0.w;
                acc[r][1] += xv.x * w1.x + xv.y * w1.y + xv.z * w1.z + xv.w * w1.w;
            }
        }
        __syncthreads();
    }
    #pragma unroll
    for (int r = 0; r < 4; r++) {
        int m = m0 + tm * 4 + r;
        if (m < TOT_N) {
            g_fcp[(kb * TOT_N + m) * 64 + tn     ] = acc[r][0];
            g_fcp[(kb * TOT_N + m) * 64 + tn + 32] = acc[r][1];
        }
    }
}

// ---------------- reduce K-split partials + bias -> g_item (float4) ----------------
__global__ void k_fcred(const float* __restrict__ b) {
    int v = blockIdx.x * blockDim.x + threadIdx.x;     // float4 index
    if (v >= TOT_N * 16) return;
    int j4 = (v & 15) * 4;
    float4 s = *(const float4*)&b[j4];
    #pragma unroll
    for (int kb = 0; kb < KSPLIT; kb++) {
        float4 p = *(const float4*)&g_fcp[kb * TOT_N * 64 + v * 4];
        s.x += p.x; s.y += p.y; s.z += p.z; s.w += p.w;
    }
    *(float4*)&g_item[v * 4] = s;
}

// ---------------- standardize: compile-time N, 2 passes ----------------
template<int ROW0, int N>
__device__ __forceinline__ void std_body(float2* red, float* mv, float* sv) {
    int tid = threadIdx.x;
    int j = tid & 63, q = tid >> 6;
    constexpr int R = (N + 15) / 16;
    float s = 0.f, ss = 0.f;
    #pragma unroll
    for (int i = 0; i < R; i++) {
        int n = q + i * 16;
        if (n < N) {
            float v = g_item[(ROW0 + n) * 64 + j];
            s += v;
            ss += v * v;
        }
    }
    red[tid] = make_float2(s, ss);
    __syncthreads();
    if (tid < 64) {
        float S = 0.f, SS = 0.f;
        #pragma unroll
        for (int k = 0; k < 16; k++) {
            float2 r = red[tid + 64 * k];
            S += r.x; SS += r.y;
        }
        float m = S / (float)N;
        float var = (SS - (float)N * m * m) / (float)(N - 1);
        mv[tid] = m;
        sv[tid] = rsqrtf(var);
    }
    __syncthreads();
    float mean = mv[j], inv = sv[j];
    #pragma unroll
    for (int i = 0; i < R; i++) {
        int n = q + i * 16;
        if (n < N) {
            int row = ROW0 + n;
            g_item[row * 64 + j] = (g_item[row * 64 + j] - mean) * inv;
        }
    }
}

__global__ void __launch_bounds__(1024) k_std() {
    __shared__ float2 red[1024];
    __shared__ float mv[64];
    __shared__ float sv[64];
    if (blockIdx.x == 0) std_body<0, CELL_N>(red, mv, sv);
    else                 std_body<CELL_N, DRUG_N>(red, mv, sv);
}

// ---------------- interact + agg fused: block per item n, 256 threads ----------------
#define IA_ROWS (128 * 65)
__global__ void __launch_bounds__(256) k_interagg(
        const int* __restrict__ cell_nbr, const int* __restrict__ drug_nbr,
        const float* __restrict__ table,
        const float* __restrict__ W, const float* __restrict__ b,
        const float* __restrict__ combw) {
    int n = blockIdx.x;
    const int* nbr;
    int item_base;
    if (n < CELL_N) { nbr = cell_nbr + n * 256; item_base = n * 64; }
    else { nbr = drug_nbr + (n - CELL_N) * 256; item_base = n * 64; }

    extern __shared__ float sm[];
    float* rows = sm;                      // 2 * IA_ROWS
    float* it   = sm + 2 * IA_ROWS;        // 64
    float* sc   = it + 64;                 // 256
    float* xr   = sc + 256;                // 128
    float* wred = xr + 128;                // 16
    float* part = wred + 16;               // 256
    __shared__ int idxs[256];

    int tid = threadIdx.x;
    int warp = tid >> 5, lane = tid & 31;
    int hop = tid >> 7, wg = tid & 127;
    idxs[tid] = nbr[tid];
    if (tid < 64) it[tid] = g_item[item_base + tid];
    __syncthreads();
    // gather 2*128 rows of 64 via LDG.128
    const float4* t4 = (const float4*)table;
    for (int e = tid; e < 2 * 128 * 16; e += 256) {
        int hk = e >> 4, q = e & 15;
        int h = hk >> 7, k = hk & 127;
        float4 v = t4[idxs[h * 128 + k] * 16 + q];
        float* dst = &rows[h * IA_ROWS + k * 65 + q * 4];
        dst[0] = v.x; dst[1] = v.y; dst[2] = v.z; dst[3] = v.w;
    }
    __syncthreads();
    // phase A: one dot per thread (hop, k=wg)
    const float* myrow = &rows[hop * IA_ROWS + wg * 65];
    float s = 0.f;
    #pragma unroll 8
    for (int d = 0; d < 64; d++) s += myrow[d] * it[d];
    float m = s;
    #pragma unroll
    for (int o = 16; o; o >>= 1) m = fmaxf(m, __shfl_xor_sync(0xffffffffu, m, o));
    if (lane == 0) wred[warp] = m;
    __syncthreads();
    int wb = (hop << 2);
    float mx = fmaxf(fmaxf(wred[wb], wred[wb + 1]), fmaxf(wred[wb + 2], wred[wb + 3]));
    float e = expf(s - mx);
    sc[tid] = e;
    float t = e;
    #pragma unroll
    for (int o = 16; o; o >>= 1) t += __shfl_xor_sync(0xffffffffu, t, o);
    if (lane == 0) wred[8 + warp] = t;
    __syncthreads();
    float inv = 1.f / (wred[8 + wb] + wred[9 + wb] + wred[10 + wb] + wred[11 + wb]);
    // phase B
    int d = wg & 63, kh = wg >> 6;
    const float* rb = &rows[hop * IA_ROWS + (kh * 64) * 65];
    const float* sb = &sc[hop * 128 + kh * 64];
    float o = 0.f;
    #pragma unroll 8
    for (int k2 = 0; k2 < 64; k2++) o += sb[k2] * rb[k2 * 65 + d];
    part[tid] = o;
    __syncthreads();
    if (wg < 64) {
        int base = hop << 7;
        xr[hop * 64 + wg] = (part[base + wg] + part[base + 64 + wg]) * inv;
    }
    __syncthreads();
    // agg: 4-way t-split
    int j = tid & 63, sl = tid >> 6;
    float ag = 0.f;
    const float* wrow = &W[j * 128 + sl * 32];
    const float* xs = &xr[sl * 32];
    #pragma unroll 8
    for (int t2 = 0; t2 < 32; t2++) ag += wrow[t2] * xs[t2];
    part[tid] = ag;
    __syncthreads();
    if (tid < 64) {
        float v = part[tid] + part[tid + 64] + part[tid + 128] + part[tid + 192] + b[tid];
        g_emb[n * 64 + tid] = v;
        it[tid] = v;
        sc[tid] = v * v;
    }
    __syncthreads();
    if (tid < 32) {
        float v = sc[tid] + sc[tid + 32];
        #pragma unroll
        for (int o2 = 16; o2; o2 >>= 1) v += __shfl_down_sync(0xffffffffu, v, o2);
        if (tid == 0) g_normsq[n] = v;
    }
    if (n < CELL_N && tid < 128) {
        float s2 = 0.f;
        #pragma unroll 8
        for (int j2 = 0; j2 < 64; j2++) s2 += combw[j2 * 128 + tid] * it[j2];
        g_U[n * 128 + tid] = s2;
    }
}

// ---------------- score (blocks 0..15, float4) + loss (block 16) ----------------
__global__ void __launch_bounds__(256) k_scoreloss(
        const int* __restrict__ data, const int* __restrict__ cell_nbr,
        const int* __restrict__ drug_nbr, float* __restrict__ out, int loss_idx) {
    int blk = blockIdx.x;
    int tid = threadIdx.x;
    if (blk < 16) {
        int bidx = blk * 256 + tid;
        int c  = data[3 * bidx];
        int d1 = data[3 * bidx + 1];
        int d2 = data[3 * bidx + 2];
        const float4* e1 = (const float4*)(g_emb + (CELL_N + d1) * 64);
        const float4* e2 = (const float4*)(g_emb + (CELL_N + d2) * 64);
        const float4* u  = (const float4*)(g_U + c * 128);
        float s = 0.f;
        #pragma unroll
        for (int t = 0; t < 16; t++) {
            float4 a = e1[t], bb = e2[t], u0 = u[t], u1 = u[16 + t];
            s += a.x * u0.x + a.y * u0.y + a.z * u0.z + a.w * u0.w;
            s += bb.x * u1.x + bb.y * u1.y + bb.z * u1.z + bb.w * u1.w;
            s -= a.x * bb.x + a.y * bb.y + a.z * bb.z + a.w * bb.w;
        }
        out[bidx] = s;
        return;
    }
    __shared__ float nsq[TOT_N];
    __shared__ float red[256];
    for (int i = tid; i < TOT_N; i += 256) nsq[i] = g_normsq[i];
    __syncthreads();
    float ir = 0.f;
    for (int bidx = tid; bidx < BATCH; bidx += 256) {
        int c  = data[3 * bidx];
        int d1 = data[3 * bidx + 1];
        int d2 = data[3 * bidx + 2];
        ir += nsq[c] + nsq[CELL_N + d1] + nsq[CELL_N + d2];
    }
    float nr = 0.f;
    for (int e = tid; e < 1536; e += 256) {
        int set = e >> 8, off = e & 255;
        int hop = set / 3, which = set - hop * 3;
        int nodeidx = data[hop * 3 + which];
        int p = (which == 0) ? cell_nbr[nodeidx * 256 + off] : drug_nbr[nodeidx * 256 + off];
        nr += g_tablesq[p];
    }
    red[tid] = 0.5f * ir + 0.5f * nr;
    __syncthreads();
    #pragma unroll
    for (int off = 128; off; off >>= 1) {
        if (tid < off) red[tid] += red[tid + off];
        __syncthreads();
    }
    if (tid == 0) out[loss_idx] = 1e-6f * red[0] / (float)BATCH;
}

// ---------------- launch ----------------
extern "C" void kernel_launch(void* const* d_in, const int* in_sizes, int n_in,
                              void* d_out, int out_size) {
    const int*   data     = (const int*)  d_in[0];
    const int*   cell_nbr = (const int*)  d_in[1];
    const int*   drug_nbr = (const int*)  d_in[2];
    const float* table    = (const float*)d_in[3];
    const float* cell_pre = (const float*)d_in[4];
    const float* drug_pre = (const float*)d_in[5];
    const float* c1w      = (const float*)d_in[6];
    const float* c1b      = (const float*)d_in[7];
    const float* c2w      = (const float*)d_in[8];
    const float* c2b      = (const float*)d_in[9];
    const float* ow       = (const float*)d_in[10];
    const float* ob       = (const float*)d_in[11];
    const float* aw       = (const float*)d_in[12];
    const float* ab       = (const float*)d_in[13];
    const float* cw       = (const float*)d_in[14];
    float* out = (float*)d_out;

    int ia_smem = (2 * IA_ROWS + 64 + 256 + 128 + 16 + 256) * 4;
    cudaFuncSetAttribute(k_interagg, cudaFuncAttributeMaxDynamicSharedMemorySize, ia_smem);

    k_conv1<<<TSQ_N + TOT_N * 2, 256>>>(cell_pre, drug_pre, c1w, c1b, table);
    k_conv2<<<TOT_N * 2, 256>>>(c2w, c2b);

    dim3 fcg(27, KSPLIT);
    k_fc<<<fcg, 256>>>(ow);
    k_fcred<<<(TOT_N * 16 + 255) / 256, 256>>>(ob);
    k_std<<<2, 1024>>>();

    k_interagg<<<TOT_N, 256, ia_smem>>>(cell_nbr, drug_nbr, table, aw, ab, cw);
    k_scoreloss<<<17, 256>>>(data, cell_nbr, drug_nbr, out, out_size - 1);
}